// round 11
// baseline (speedup 1.0000x reference)
#include <cuda_runtime.h>
#include <cuda_bf16.h>

#define N_NODES 100000
#define N_EDGES 1600000
#define IN_CH 64
#define HID 128
#define SCAN_BLOCKS 98   // ceil(100000/1024)

typedef unsigned int u32;

// Scratch (static device globals; allocation-free per harness rules)
__device__ int   g_deg[N_NODES];
__device__ int   g_cursor[N_NODES];
__device__ int   g_row_ptr[N_NODES + 1];
__device__ int   g_srcs[N_EDGES];
__device__ int   g_bsum[SCAN_BLOCKS];
__device__ int   g_boff[SCAN_BLOCKS + 1];
// activations as separate bf16 hi/lo planes (split once, copied raw into GEMM)
__device__ __nv_bfloat16 g_xhi[(size_t)N_NODES * IN_CH], g_xlo[(size_t)N_NODES * IN_CH];
__device__ __nv_bfloat16 g_m0hi[(size_t)N_NODES * IN_CH], g_m0lo[(size_t)N_NODES * IN_CH];
__device__ __nv_bfloat16 g_h1hi[(size_t)N_NODES * HID], g_h1lo[(size_t)N_NODES * HID];
__device__ __nv_bfloat16 g_m1hi[(size_t)N_NODES * HID], g_m1lo[(size_t)N_NODES * HID];
// pre-split transposed weights: B[n][k] = W[k][n], bf16 hi/lo, row pitch Ktot
__device__ __nv_bfloat16 g_B0hi[128 * 128], g_B0lo[128 * 128];
__device__ __nv_bfloat16 g_B1hi[128 * 256], g_B1lo[128 * 256];

__device__ __forceinline__ void split_bf16(float v, unsigned short& h, unsigned short& l) {
    __nv_bfloat16 bh = __float2bfloat16(v);
    float r = v - __bfloat162float(bh);
    __nv_bfloat16 bl = __float2bfloat16(r);
    h = __bfloat16_as_ushort(bh);
    l = __bfloat16_as_ushort(bl);
}
__device__ __forceinline__ float bf_lo_f(u32 p) { return __uint_as_float(p << 16); }
__device__ __forceinline__ float bf_hi_f(u32 p) { return __uint_as_float(p & 0xFFFF0000u); }

__device__ __forceinline__ void mma_bf16(float* c, const u32* a, u32 b0, u32 b1) {
    asm volatile(
        "mma.sync.aligned.m16n8k16.row.col.f32.bf16.bf16.f32 "
        "{%0,%1,%2,%3}, {%4,%5,%6,%7}, {%8,%9}, {%0,%1,%2,%3};"
        : "+f"(c[0]), "+f"(c[1]), "+f"(c[2]), "+f"(c[3])
        : "r"(a[0]), "r"(a[1]), "r"(a[2]), "r"(a[3]), "r"(b0), "r"(b1));
}

// ---------------------------------------------------------------------------
// Init: zero degree array + transpose/split both weight matrices
// ---------------------------------------------------------------------------
__global__ void init_kernel(const float* __restrict__ Wn0,
                            const float* __restrict__ Ws0,
                            const float* __restrict__ Wn1,
                            const float* __restrict__ Ws1) {
    int i = blockIdx.x * blockDim.x + threadIdx.x;
    if (i < N_NODES) g_deg[i] = 0;
    if (i < 128 * 256) {
        int n = i >> 8, kk = i & 255;
        float w = (kk < 128) ? Wn1[kk * HID + n] : Ws1[(kk - 128) * HID + n];
        unsigned short h, l;
        split_bf16(w, h, l);
        g_B1hi[i] = __ushort_as_bfloat16(h);
        g_B1lo[i] = __ushort_as_bfloat16(l);
    }
    if (i < 128 * 128) {
        int n = i >> 7, kk = i & 127;
        float w = (kk < 64) ? Wn0[kk * HID + n] : Ws0[(kk - 64) * HID + n];
        unsigned short h, l;
        split_bf16(w, h, l);
        g_B0hi[i] = __ushort_as_bfloat16(h);
        g_B0lo[i] = __ushort_as_bfloat16(l);
    }
}

// ---------------------------------------------------------------------------
// CSR build
// ---------------------------------------------------------------------------
__global__ void hist_kernel(const int* __restrict__ ei) {
    int e = blockIdx.x * blockDim.x + threadIdx.x;
    if (e >= N_EDGES) return;
    atomicAdd(&g_deg[__ldg(&ei[e + N_EDGES])], 1);
}
__global__ __launch_bounds__(1024)
void scan_phase1_kernel() {
    __shared__ int wsum[32];
    int t = threadIdx.x, lane = t & 31, warp = t >> 5;
    int i = blockIdx.x * 1024 + t;
    int v = (i < N_NODES) ? g_deg[i] : 0;
    int inc = v;
#pragma unroll
    for (int off = 1; off < 32; off <<= 1) {
        int n = __shfl_up_sync(0xFFFFFFFF, inc, off);
        if (lane >= off) inc += n;
    }
    if (lane == 31) wsum[warp] = inc;
    __syncthreads();
    if (warp == 0) {
        int w = (lane < 32) ? wsum[lane] : 0;
#pragma unroll
        for (int off = 1; off < 32; off <<= 1) {
            int n = __shfl_up_sync(0xFFFFFFFF, w, off);
            if (lane >= off) w += n;
        }
        wsum[lane] = w;
    }
    __syncthreads();
    int winc = inc + ((warp > 0) ? wsum[warp - 1] : 0);
    if (i < N_NODES) g_cursor[i] = winc;
    if (t == 1023) g_bsum[blockIdx.x] = winc;
}
__global__ void scan_phase2_kernel() {
    __shared__ int sm[SCAN_BLOCKS];
    int t = threadIdx.x;
    if (t < SCAN_BLOCKS) sm[t] = g_bsum[t];
    __syncthreads();
    if (t == 0) {
        int acc = 0;
        for (int i = 0; i < SCAN_BLOCKS; i++) {
            g_boff[i] = acc;
            acc += sm[i];
        }
        g_boff[SCAN_BLOCKS] = acc;
        g_row_ptr[N_NODES] = acc;
    }
}
__global__ __launch_bounds__(1024)
void scan_phase3_kernel() {
    int i = blockIdx.x * 1024 + threadIdx.x;
    if (i >= N_NODES) return;
    int ex = g_boff[blockIdx.x] + g_cursor[i] - g_deg[i];
    g_row_ptr[i] = ex;
    g_cursor[i]  = ex;
}
__global__ void fill_kernel(const int* __restrict__ ei) {
    int e = blockIdx.x * blockDim.x + threadIdx.x;
    if (e >= N_EDGES) return;
    int src = __ldg(&ei[e]);
    int dst = __ldg(&ei[e + N_EDGES]);
    int pos = atomicAdd(&g_cursor[dst], 1);
    g_srcs[pos] = src;
}

// ---------------------------------------------------------------------------
// Gather0: mean of x over in-edges -> m0 hi/lo planes; ALSO splits own x row
// into xhi/xlo (fused prep_x: x row is L2-hot from gathering).
// ---------------------------------------------------------------------------
__global__ void gather0_kernel(const float* __restrict__ x) {
    int node = blockIdx.x * 8 + (threadIdx.x >> 5);
    if (node >= N_NODES) return;
    int lane = threadIdx.x & 31;
    int beg = g_row_ptr[node], end = g_row_ptr[node + 1];
    float2 acc = make_float2(0.f, 0.f);
#pragma unroll 8
    for (int e = beg; e < end; e++) {
        int s = __ldg(&g_srcs[e]);
        float2 v = *(const float2*)(x + (size_t)s * IN_CH + lane * 2);
        acc.x += v.x; acc.y += v.y;
    }
    float inv = 1.0f / fmaxf((float)(end - beg), 1.0f);
    size_t o = (size_t)node * IN_CH + lane * 2;
    {
        unsigned short h0, l0, h1, l1;
        split_bf16(acc.x * inv, h0, l0);
        split_bf16(acc.y * inv, h1, l1);
        *(u32*)(g_m0hi + o) = (u32)h0 | ((u32)h1 << 16);
        *(u32*)(g_m0lo + o) = (u32)l0 | ((u32)l1 << 16);
    }
    {   // fused x split (own row)
        float2 v = *(const float2*)(x + o);
        unsigned short h0, l0, h1, l1;
        split_bf16(v.x, h0, l0);
        split_bf16(v.y, h1, l1);
        *(u32*)(g_xhi + o) = (u32)h0 | ((u32)h1 << 16);
        *(u32*)(g_xlo + o) = (u32)l0 | ((u32)l1 << 16);
    }
}
__global__ void gather1_kernel() {
    int node = blockIdx.x * 8 + (threadIdx.x >> 5);
    if (node >= N_NODES) return;
    int lane = threadIdx.x & 31;
    int beg = g_row_ptr[node], end = g_row_ptr[node + 1];
    float4 acc = make_float4(0.f, 0.f, 0.f, 0.f);
#pragma unroll 8
    for (int e = beg; e < end; e++) {
        int s = __ldg(&g_srcs[e]);
        uint2 vh = *(const uint2*)(g_h1hi + (size_t)s * HID + lane * 4);
        uint2 vl = *(const uint2*)(g_h1lo + (size_t)s * HID + lane * 4);
        acc.x += bf_lo_f(vh.x) + bf_lo_f(vl.x);
        acc.y += bf_hi_f(vh.x) + bf_hi_f(vl.x);
        acc.z += bf_lo_f(vh.y) + bf_lo_f(vl.y);
        acc.w += bf_hi_f(vh.y) + bf_hi_f(vl.y);
    }
    float inv = 1.0f / fmaxf((float)(end - beg), 1.0f);
    unsigned short h[4], l[4];
    split_bf16(acc.x * inv, h[0], l[0]);
    split_bf16(acc.y * inv, h[1], l[1]);
    split_bf16(acc.z * inv, h[2], l[2]);
    split_bf16(acc.w * inv, h[3], l[3]);
    size_t o = (size_t)node * HID + lane * 4;
    *(uint2*)(g_m1hi + o) = make_uint2((u32)h[0] | ((u32)h[1] << 16),
                                       (u32)h[2] | ((u32)h[3] << 16));
    *(uint2*)(g_m1lo + o) = make_uint2((u32)l[0] | ((u32)l[1] << 16),
                                       (u32)l[2] | ((u32)l[3] << 16));
}

// ---------------------------------------------------------------------------
// HMMA bf16x3-split GEMM: C[128 nodes][128 out] = [A0|A1] @ B^T (fp32 accum).
// __launch_bounds__(256, 2) guarantees 2 CTAs/SM for staging/MMA overlap.
// ---------------------------------------------------------------------------
#define PA 72   // smem pitch (bf16 elements)

__global__ __launch_bounds__(256, 2)
void mma_layer_kernel(const __nv_bfloat16* __restrict__ A0hi,
                      const __nv_bfloat16* __restrict__ A0lo,
                      const __nv_bfloat16* __restrict__ A1hi,
                      const __nv_bfloat16* __restrict__ A1lo,
                      int rowlen, int nchunk,
                      const __nv_bfloat16* __restrict__ Bhi,
                      const __nv_bfloat16* __restrict__ Blo,
                      int Ktot,
                      const float* __restrict__ bias,
                      __nv_bfloat16* __restrict__ h1hi_out,
                      __nv_bfloat16* __restrict__ h1lo_out,
                      const float* __restrict__ fcw,
                      const float* __restrict__ fcb,
                      float* __restrict__ out) {
    extern __shared__ char smem[];
    __nv_bfloat16* sAhi = (__nv_bfloat16*)smem;
    __nv_bfloat16* sAlo = sAhi + 128 * PA;
    __nv_bfloat16* sBhi = sAlo + 128 * PA;
    __nv_bfloat16* sBlo = sBhi + 128 * PA;
    float* sBias = (float*)(sBlo + 128 * PA);
    float* sFc   = sBias + 128;

    int t = threadIdx.x;
    int wid = t >> 5, lane = t & 31;
    int g = lane >> 2, tig = lane & 3;
    int wm = wid & 3, wn = wid >> 2;
    int nodeBase = blockIdx.x * 128;

    if (t < 128) sBias[t] = bias[t];
    if (out && t < 256) sFc[t] = fcw[t];

    float c[2][8][4];
#pragma unroll
    for (int mt = 0; mt < 2; mt++)
#pragma unroll
        for (int nt = 0; nt < 8; nt++)
#pragma unroll
            for (int q = 0; q < 4; q++) c[mt][nt][q] = 0.f;

    int half = nchunk >> 1;
    int srow = t >> 1;
    int skq  = (t & 1) * 32;

    for (int ch = 0; ch < nchunk; ch++) {
        const __nv_bfloat16* srcHi = (ch < half) ? A0hi : A1hi;
        const __nv_bfloat16* srcLo = (ch < half) ? A0lo : A1lo;
        int kofs = ((ch < half) ? ch : ch - half) * 64;
        __syncthreads();
        // ---- stage A: raw uint4 copies from hi/lo planes ----
        {
            int gn = nodeBase + srow;
            __nv_bfloat16* dh = sAhi + srow * PA + skq;
            __nv_bfloat16* dl = sAlo + srow * PA + skq;
            if (gn < N_NODES) {
                const __nv_bfloat16* ph = srcHi + (size_t)gn * rowlen + kofs + skq;
                const __nv_bfloat16* pl = srcLo + (size_t)gn * rowlen + kofs + skq;
#pragma unroll
                for (int q = 0; q < 4; q++) {
                    *(uint4*)(dh + q * 8) = *(const uint4*)(ph + q * 8);
                    *(uint4*)(dl + q * 8) = *(const uint4*)(pl + q * 8);
                }
            } else {
                uint4 z = make_uint4(0, 0, 0, 0);
#pragma unroll
                for (int q = 0; q < 4; q++) {
                    *(uint4*)(dh + q * 8) = z;
                    *(uint4*)(dl + q * 8) = z;
                }
            }
        }
        // ---- stage B ----
        {
            const __nv_bfloat16* ph = Bhi + (size_t)srow * Ktot + ch * 64 + skq;
            const __nv_bfloat16* pl = Blo + (size_t)srow * Ktot + ch * 64 + skq;
            __nv_bfloat16* dh = sBhi + srow * PA + skq;
            __nv_bfloat16* dl = sBlo + srow * PA + skq;
#pragma unroll
            for (int q = 0; q < 4; q++) {
                *(uint4*)(dh + q * 8) = *(const uint4*)(ph + q * 8);
                *(uint4*)(dl + q * 8) = *(const uint4*)(pl + q * 8);
            }
        }
        __syncthreads();

        // ---- compute: 4 k16 steps ----
#pragma unroll
        for (int ks = 0; ks < 4; ks++) {
            int k0 = ks * 16;
            u32 ahi[2][4], alo[2][4];
#pragma unroll
            for (int mt = 0; mt < 2; mt++) {
                int r = wm * 32 + mt * 16 + g;
                const __nv_bfloat16* base = sAhi + r * PA + k0 + tig * 2;
                ahi[mt][0] = *(const u32*)base;
                ahi[mt][1] = *(const u32*)(base + 8 * PA);
                ahi[mt][2] = *(const u32*)(base + 8);
                ahi[mt][3] = *(const u32*)(base + 8 * PA + 8);
                const __nv_bfloat16* basel = sAlo + r * PA + k0 + tig * 2;
                alo[mt][0] = *(const u32*)basel;
                alo[mt][1] = *(const u32*)(basel + 8 * PA);
                alo[mt][2] = *(const u32*)(basel + 8);
                alo[mt][3] = *(const u32*)(basel + 8 * PA + 8);
            }
#pragma unroll
            for (int nt = 0; nt < 8; nt++) {
                int n = wn * 64 + nt * 8 + g;
                const __nv_bfloat16* bb = sBhi + n * PA + k0 + tig * 2;
                u32 bh0 = *(const u32*)bb;
                u32 bh1 = *(const u32*)(bb + 8);
                const __nv_bfloat16* bl = sBlo + n * PA + k0 + tig * 2;
                u32 bl0 = *(const u32*)bl;
                u32 bl1 = *(const u32*)(bl + 8);
#pragma unroll
                for (int mt = 0; mt < 2; mt++) {
                    mma_bf16(c[mt][nt], ahi[mt], bh0, bh1);
                    mma_bf16(c[mt][nt], alo[mt], bh0, bh1);
                    mma_bf16(c[mt][nt], ahi[mt], bl0, bl1);
                }
            }
        }
    }

    // ---- epilogue ----
    if (h1hi_out) {
#pragma unroll
        for (int mt = 0; mt < 2; mt++) {
            int r0 = nodeBase + wm * 32 + mt * 16 + g;
            int r1 = r0 + 8;
#pragma unroll
            for (int nt = 0; nt < 8; nt++) {
                int col = wn * 64 + nt * 8 + tig * 2;
                if (r0 < N_NODES) {
                    float v0 = fmaxf(c[mt][nt][0] + sBias[col], 0.f);
                    float v1 = fmaxf(c[mt][nt][1] + sBias[col + 1], 0.f);
                    unsigned short h0, l0, h1, l1;
                    split_bf16(v0, h0, l0);
                    split_bf16(v1, h1, l1);
                    size_t o = (size_t)r0 * HID + col;
                    *(u32*)(h1hi_out + o) = (u32)h0 | ((u32)h1 << 16);
                    *(u32*)(h1lo_out + o) = (u32)l0 | ((u32)l1 << 16);
                }
                if (r1 < N_NODES) {
                    float v0 = fmaxf(c[mt][nt][2] + sBias[col], 0.f);
                    float v1 = fmaxf(c[mt][nt][3] + sBias[col + 1], 0.f);
                    unsigned short h0, l0, h1, l1;
                    split_bf16(v0, h0, l0);
                    split_bf16(v1, h1, l1);
                    size_t o = (size_t)r1 * HID + col;
                    *(u32*)(h1hi_out + o) = (u32)h0 | ((u32)h1 << 16);
                    *(u32*)(h1lo_out + o) = (u32)l0 | ((u32)l1 << 16);
                }
            }
        }
    } else {
        float fb0 = __ldg(&fcb[0]), fb1 = __ldg(&fcb[1]);
#pragma unroll
        for (int mt = 0; mt < 2; mt++) {
            float p0a = 0.f, p1a = 0.f, p0b = 0.f, p1b = 0.f;
#pragma unroll
            for (int nt = 0; nt < 8; nt++) {
                int col = wn * 64 + nt * 8 + tig * 2;
                float h0 = fmaxf(c[mt][nt][0] + sBias[col], 0.f);
                float h1 = fmaxf(c[mt][nt][1] + sBias[col + 1], 0.f);
                float h2 = fmaxf(c[mt][nt][2] + sBias[col], 0.f);
                float h3 = fmaxf(c[mt][nt][3] + sBias[col + 1], 0.f);
                p0a += h0 * sFc[col * 2]     + h1 * sFc[(col + 1) * 2];
                p1a += h0 * sFc[col * 2 + 1] + h1 * sFc[(col + 1) * 2 + 1];
                p0b += h2 * sFc[col * 2]     + h3 * sFc[(col + 1) * 2];
                p1b += h2 * sFc[col * 2 + 1] + h3 * sFc[(col + 1) * 2 + 1];
            }
#pragma unroll
            for (int off = 1; off <= 2; off <<= 1) {
                p0a += __shfl_xor_sync(0xFFFFFFFF, p0a, off);
                p1a += __shfl_xor_sync(0xFFFFFFFF, p1a, off);
                p0b += __shfl_xor_sync(0xFFFFFFFF, p0b, off);
                p1b += __shfl_xor_sync(0xFFFFFFFF, p1b, off);
            }
            int r0 = wm * 32 + mt * 16 + g;
            if (tig == 0) {
                float* part = sFc + 256;
                part[(wn * 128 + r0) * 2 + 0] = p0a;
                part[(wn * 128 + r0) * 2 + 1] = p1a;
                part[(wn * 128 + r0 + 8) * 2 + 0] = p0b;
                part[(wn * 128 + r0 + 8) * 2 + 1] = p1b;
            }
        }
        __syncthreads();
        if (t < 256) {
            float* part = sFc + 256;
            int row = t >> 1, chn = t & 1;
            float v = part[row * 2 + chn] + part[(128 + row) * 2 + chn];
            int node = nodeBase + row;
            if (node < N_NODES)
                out[(size_t)node * 2 + chn] = v + ((chn == 0) ? fb0 : fb1);
        }
    }
}

#define SMEM_MMA_TOTAL (4 * 128 * PA * 2 + (128 + 256 + 512) * 4)

// ---------------------------------------------------------------------------
extern "C" void kernel_launch(void* const* d_in, const int* in_sizes, int n_in,
                              void* d_out, int out_size) {
    const float* x   = (const float*)d_in[0];
    const int*   ei  = (const int*)d_in[1];     // int32 (JAX x64 disabled)
    const float* Wn0 = (const float*)d_in[2];
    const float* Ws0 = (const float*)d_in[3];
    const float* b0  = (const float*)d_in[4];
    const float* Wn1 = (const float*)d_in[5];
    const float* Ws1 = (const float*)d_in[6];
    const float* b1  = (const float*)d_in[7];
    const float* fcw = (const float*)d_in[8];
    const float* fcb = (const float*)d_in[9];
    float* out = (float*)d_out;

    void *p_xhi, *p_xlo, *p_m0hi, *p_m0lo, *p_h1hi, *p_h1lo, *p_m1hi, *p_m1lo;
    void *p_B0hi, *p_B0lo, *p_B1hi, *p_B1lo;
    cudaGetSymbolAddress(&p_xhi, g_xhi);
    cudaGetSymbolAddress(&p_xlo, g_xlo);
    cudaGetSymbolAddress(&p_m0hi, g_m0hi);
    cudaGetSymbolAddress(&p_m0lo, g_m0lo);
    cudaGetSymbolAddress(&p_h1hi, g_h1hi);
    cudaGetSymbolAddress(&p_h1lo, g_h1lo);
    cudaGetSymbolAddress(&p_m1hi, g_m1hi);
    cudaGetSymbolAddress(&p_m1lo, g_m1lo);
    cudaGetSymbolAddress(&p_B0hi, g_B0hi);
    cudaGetSymbolAddress(&p_B0lo, g_B0lo);
    cudaGetSymbolAddress(&p_B1hi, g_B1hi);
    cudaGetSymbolAddress(&p_B1lo, g_B1lo);

    // Init (zero deg + weight split) then CSR build
    init_kernel<<<(N_NODES + 255) / 256, 256>>>(Wn0, Ws0, Wn1, Ws1);
    hist_kernel<<<(N_EDGES + 255) / 256, 256>>>(ei);
    scan_phase1_kernel<<<SCAN_BLOCKS, 1024>>>();
    scan_phase2_kernel<<<1, 128>>>();
    scan_phase3_kernel<<<SCAN_BLOCKS, 1024>>>();
    fill_kernel<<<(N_EDGES + 255) / 256, 256>>>(ei);

    cudaFuncSetAttribute(mma_layer_kernel,
                         cudaFuncAttributeMaxDynamicSharedMemorySize, SMEM_MMA_TOTAL);
    int gemmBlocks = (N_NODES + 127) / 128;   // 782

    // Layer 0: h1 = relu([mean0|x] @ [Wn0;Ws0] + b0)   (outputs hi/lo planes)
    gather0_kernel<<<(N_NODES + 7) / 8, 256>>>(x);
    mma_layer_kernel<<<gemmBlocks, 256, SMEM_MMA_TOTAL>>>(
        (const __nv_bfloat16*)p_m0hi, (const __nv_bfloat16*)p_m0lo,
        (const __nv_bfloat16*)p_xhi,  (const __nv_bfloat16*)p_xlo,
        IN_CH, 2,
        (const __nv_bfloat16*)p_B0hi, (const __nv_bfloat16*)p_B0lo, 128,
        b0,
        (__nv_bfloat16*)p_h1hi, (__nv_bfloat16*)p_h1lo,
        nullptr, nullptr, nullptr);

    // Layer 1 + fused FC
    gather1_kernel<<<(N_NODES + 7) / 8, 256>>>();
    mma_layer_kernel<<<gemmBlocks, 256, SMEM_MMA_TOTAL>>>(
        (const __nv_bfloat16*)p_m1hi, (const __nv_bfloat16*)p_m1lo,
        (const __nv_bfloat16*)p_h1hi, (const __nv_bfloat16*)p_h1lo,
        HID, 4,
        (const __nv_bfloat16*)p_B1hi, (const __nv_bfloat16*)p_B1lo, 256,
        b1,
        nullptr, nullptr,
        fcw, fcb, out);
}

// round 12
// speedup vs baseline: 1.0397x; 1.0397x over previous
#include <cuda_runtime.h>
#include <cuda_bf16.h>

#define N_NODES 100000
#define N_EDGES 1600000
#define IN_CH 64
#define HID 128
#define SCAN_BLOCKS 98   // ceil(100000/1024)

typedef unsigned int u32;

// Scratch (static device globals; allocation-free per harness rules)
__device__ int   g_deg[N_NODES];
__device__ int   g_cursor[N_NODES];
__device__ int   g_row_ptr[N_NODES + 1];
__device__ int   g_srcs[N_EDGES];
__device__ int   g_bsum[SCAN_BLOCKS];
__device__ int   g_boff[SCAN_BLOCKS + 1];
// activations as separate bf16 hi/lo planes (split once, copied raw into GEMM)
__device__ __nv_bfloat16 g_xhi[(size_t)N_NODES * IN_CH], g_xlo[(size_t)N_NODES * IN_CH];
__device__ __nv_bfloat16 g_m0hi[(size_t)N_NODES * IN_CH], g_m0lo[(size_t)N_NODES * IN_CH];
__device__ __nv_bfloat16 g_h1hi[(size_t)N_NODES * HID], g_h1lo[(size_t)N_NODES * HID];
__device__ __nv_bfloat16 g_m1hi[(size_t)N_NODES * HID], g_m1lo[(size_t)N_NODES * HID];
// pre-split transposed weights: B[n][k] = W[k][n], bf16 hi/lo, row pitch Ktot
__device__ __nv_bfloat16 g_B0hi[128 * 128], g_B0lo[128 * 128];
__device__ __nv_bfloat16 g_B1hi[128 * 256], g_B1lo[128 * 256];

__device__ __forceinline__ void split_bf16(float v, unsigned short& h, unsigned short& l) {
    __nv_bfloat16 bh = __float2bfloat16(v);
    float r = v - __bfloat162float(bh);
    __nv_bfloat16 bl = __float2bfloat16(r);
    h = __bfloat16_as_ushort(bh);
    l = __bfloat16_as_ushort(bl);
}
__device__ __forceinline__ float bf_lo_f(u32 p) { return __uint_as_float(p << 16); }
__device__ __forceinline__ float bf_hi_f(u32 p) { return __uint_as_float(p & 0xFFFF0000u); }

__device__ __forceinline__ void mma_bf16(float* c, const u32* a, u32 b0, u32 b1) {
    asm volatile(
        "mma.sync.aligned.m16n8k16.row.col.f32.bf16.bf16.f32 "
        "{%0,%1,%2,%3}, {%4,%5,%6,%7}, {%8,%9}, {%0,%1,%2,%3};"
        : "+f"(c[0]), "+f"(c[1]), "+f"(c[2]), "+f"(c[3])
        : "r"(a[0]), "r"(a[1]), "r"(a[2]), "r"(a[3]), "r"(b0), "r"(b1));
}

// ---------------------------------------------------------------------------
// Init: zero degree array + transpose/split both weight matrices
// ---------------------------------------------------------------------------
__global__ void init_kernel(const float* __restrict__ Wn0,
                            const float* __restrict__ Ws0,
                            const float* __restrict__ Wn1,
                            const float* __restrict__ Ws1) {
    int i = blockIdx.x * blockDim.x + threadIdx.x;
    if (i < N_NODES) g_deg[i] = 0;
    if (i < 128 * 256) {
        int n = i >> 8, kk = i & 255;
        float w = (kk < 128) ? Wn1[kk * HID + n] : Ws1[(kk - 128) * HID + n];
        unsigned short h, l;
        split_bf16(w, h, l);
        g_B1hi[i] = __ushort_as_bfloat16(h);
        g_B1lo[i] = __ushort_as_bfloat16(l);
    }
    if (i < 128 * 128) {
        int n = i >> 7, kk = i & 127;
        float w = (kk < 64) ? Wn0[kk * HID + n] : Ws0[(kk - 64) * HID + n];
        unsigned short h, l;
        split_bf16(w, h, l);
        g_B0hi[i] = __ushort_as_bfloat16(h);
        g_B0lo[i] = __ushort_as_bfloat16(l);
    }
}

// ---------------------------------------------------------------------------
// CSR build
// ---------------------------------------------------------------------------
__global__ void hist_kernel(const int* __restrict__ ei) {
    int e = blockIdx.x * blockDim.x + threadIdx.x;
    if (e >= N_EDGES) return;
    atomicAdd(&g_deg[__ldg(&ei[e + N_EDGES])], 1);
}
__global__ __launch_bounds__(1024)
void scan_phase1_kernel() {
    __shared__ int wsum[32];
    int t = threadIdx.x, lane = t & 31, warp = t >> 5;
    int i = blockIdx.x * 1024 + t;
    int v = (i < N_NODES) ? g_deg[i] : 0;
    int inc = v;
#pragma unroll
    for (int off = 1; off < 32; off <<= 1) {
        int n = __shfl_up_sync(0xFFFFFFFF, inc, off);
        if (lane >= off) inc += n;
    }
    if (lane == 31) wsum[warp] = inc;
    __syncthreads();
    if (warp == 0) {
        int w = (lane < 32) ? wsum[lane] : 0;
#pragma unroll
        for (int off = 1; off < 32; off <<= 1) {
            int n = __shfl_up_sync(0xFFFFFFFF, w, off);
            if (lane >= off) w += n;
        }
        wsum[lane] = w;
    }
    __syncthreads();
    int winc = inc + ((warp > 0) ? wsum[warp - 1] : 0);
    if (i < N_NODES) g_cursor[i] = winc;
    if (t == 1023) g_bsum[blockIdx.x] = winc;
}
__global__ void scan_phase2_kernel() {
    __shared__ int sm[SCAN_BLOCKS];
    int t = threadIdx.x;
    if (t < SCAN_BLOCKS) sm[t] = g_bsum[t];
    __syncthreads();
    if (t == 0) {
        int acc = 0;
        for (int i = 0; i < SCAN_BLOCKS; i++) {
            g_boff[i] = acc;
            acc += sm[i];
        }
        g_boff[SCAN_BLOCKS] = acc;
        g_row_ptr[N_NODES] = acc;
    }
}
__global__ __launch_bounds__(1024)
void scan_phase3_kernel() {
    int i = blockIdx.x * 1024 + threadIdx.x;
    if (i >= N_NODES) return;
    int ex = g_boff[blockIdx.x] + g_cursor[i] - g_deg[i];
    g_row_ptr[i] = ex;
    g_cursor[i]  = ex;
}
__global__ void fill_kernel(const int* __restrict__ ei) {
    int e = blockIdx.x * blockDim.x + threadIdx.x;
    if (e >= N_EDGES) return;
    int src = __ldg(&ei[e]);
    int dst = __ldg(&ei[e + N_EDGES]);
    int pos = atomicAdd(&g_cursor[dst], 1);
    g_srcs[pos] = src;
}

// ---------------------------------------------------------------------------
// Gather0: mean of x over in-edges -> m0 hi/lo planes; ALSO splits own x row
// into xhi/xlo (fused prep_x: x row is L2-hot from gathering).
// ---------------------------------------------------------------------------
__global__ void gather0_kernel(const float* __restrict__ x) {
    int node = blockIdx.x * 8 + (threadIdx.x >> 5);
    if (node >= N_NODES) return;
    int lane = threadIdx.x & 31;
    int beg = g_row_ptr[node], end = g_row_ptr[node + 1];
    float2 acc = make_float2(0.f, 0.f);
#pragma unroll 8
    for (int e = beg; e < end; e++) {
        int s = __ldg(&g_srcs[e]);
        float2 v = *(const float2*)(x + (size_t)s * IN_CH + lane * 2);
        acc.x += v.x; acc.y += v.y;
    }
    float inv = 1.0f / fmaxf((float)(end - beg), 1.0f);
    size_t o = (size_t)node * IN_CH + lane * 2;
    {
        unsigned short h0, l0, h1, l1;
        split_bf16(acc.x * inv, h0, l0);
        split_bf16(acc.y * inv, h1, l1);
        *(u32*)(g_m0hi + o) = (u32)h0 | ((u32)h1 << 16);
        *(u32*)(g_m0lo + o) = (u32)l0 | ((u32)l1 << 16);
    }
    {   // fused x split (own row)
        float2 v = *(const float2*)(x + o);
        unsigned short h0, l0, h1, l1;
        split_bf16(v.x, h0, l0);
        split_bf16(v.y, h1, l1);
        *(u32*)(g_xhi + o) = (u32)h0 | ((u32)h1 << 16);
        *(u32*)(g_xlo + o) = (u32)l0 | ((u32)l1 << 16);
    }
}
__global__ void gather1_kernel() {
    int node = blockIdx.x * 8 + (threadIdx.x >> 5);
    if (node >= N_NODES) return;
    int lane = threadIdx.x & 31;
    int beg = g_row_ptr[node], end = g_row_ptr[node + 1];
    float4 acc = make_float4(0.f, 0.f, 0.f, 0.f);
#pragma unroll 8
    for (int e = beg; e < end; e++) {
        int s = __ldg(&g_srcs[e]);
        uint2 vh = *(const uint2*)(g_h1hi + (size_t)s * HID + lane * 4);
        uint2 vl = *(const uint2*)(g_h1lo + (size_t)s * HID + lane * 4);
        acc.x += bf_lo_f(vh.x) + bf_lo_f(vl.x);
        acc.y += bf_hi_f(vh.x) + bf_hi_f(vl.x);
        acc.z += bf_lo_f(vh.y) + bf_lo_f(vl.y);
        acc.w += bf_hi_f(vh.y) + bf_hi_f(vl.y);
    }
    float inv = 1.0f / fmaxf((float)(end - beg), 1.0f);
    unsigned short h[4], l[4];
    split_bf16(acc.x * inv, h[0], l[0]);
    split_bf16(acc.y * inv, h[1], l[1]);
    split_bf16(acc.z * inv, h[2], l[2]);
    split_bf16(acc.w * inv, h[3], l[3]);
    size_t o = (size_t)node * HID + lane * 4;
    *(uint2*)(g_m1hi + o) = make_uint2((u32)h[0] | ((u32)h[1] << 16),
                                       (u32)h[2] | ((u32)h[3] << 16));
    *(uint2*)(g_m1lo + o) = make_uint2((u32)l[0] | ((u32)l[1] << 16),
                                       (u32)l[2] | ((u32)l[3] << 16));
}

// ---------------------------------------------------------------------------
// HMMA bf16x3-split GEMM: C[128 nodes][128 out] = [A0|A1] @ B^T (fp32 accum).
// NOTE: no minBlocks clause — (256,2) capped regs at 128 and caused spills (R11).
// ---------------------------------------------------------------------------
#define PA 72   // smem pitch (bf16 elements)

__global__ __launch_bounds__(256)
void mma_layer_kernel(const __nv_bfloat16* __restrict__ A0hi,
                      const __nv_bfloat16* __restrict__ A0lo,
                      const __nv_bfloat16* __restrict__ A1hi,
                      const __nv_bfloat16* __restrict__ A1lo,
                      int rowlen, int nchunk,
                      const __nv_bfloat16* __restrict__ Bhi,
                      const __nv_bfloat16* __restrict__ Blo,
                      int Ktot,
                      const float* __restrict__ bias,
                      __nv_bfloat16* __restrict__ h1hi_out,
                      __nv_bfloat16* __restrict__ h1lo_out,
                      const float* __restrict__ fcw,
                      const float* __restrict__ fcb,
                      float* __restrict__ out) {
    extern __shared__ char smem[];
    __nv_bfloat16* sAhi = (__nv_bfloat16*)smem;
    __nv_bfloat16* sAlo = sAhi + 128 * PA;
    __nv_bfloat16* sBhi = sAlo + 128 * PA;
    __nv_bfloat16* sBlo = sBhi + 128 * PA;
    float* sBias = (float*)(sBlo + 128 * PA);
    float* sFc   = sBias + 128;

    int t = threadIdx.x;
    int wid = t >> 5, lane = t & 31;
    int g = lane >> 2, tig = lane & 3;
    int wm = wid & 3, wn = wid >> 2;
    int nodeBase = blockIdx.x * 128;

    if (t < 128) sBias[t] = bias[t];
    if (out && t < 256) sFc[t] = fcw[t];

    float c[2][8][4];
#pragma unroll
    for (int mt = 0; mt < 2; mt++)
#pragma unroll
        for (int nt = 0; nt < 8; nt++)
#pragma unroll
            for (int q = 0; q < 4; q++) c[mt][nt][q] = 0.f;

    int half = nchunk >> 1;
    int srow = t >> 1;
    int skq  = (t & 1) * 32;

    for (int ch = 0; ch < nchunk; ch++) {
        const __nv_bfloat16* srcHi = (ch < half) ? A0hi : A1hi;
        const __nv_bfloat16* srcLo = (ch < half) ? A0lo : A1lo;
        int kofs = ((ch < half) ? ch : ch - half) * 64;
        __syncthreads();
        // ---- stage A: raw uint4 copies from hi/lo planes ----
        {
            int gn = nodeBase + srow;
            __nv_bfloat16* dh = sAhi + srow * PA + skq;
            __nv_bfloat16* dl = sAlo + srow * PA + skq;
            if (gn < N_NODES) {
                const __nv_bfloat16* ph = srcHi + (size_t)gn * rowlen + kofs + skq;
                const __nv_bfloat16* pl = srcLo + (size_t)gn * rowlen + kofs + skq;
#pragma unroll
                for (int q = 0; q < 4; q++) {
                    *(uint4*)(dh + q * 8) = *(const uint4*)(ph + q * 8);
                    *(uint4*)(dl + q * 8) = *(const uint4*)(pl + q * 8);
                }
            } else {
                uint4 z = make_uint4(0, 0, 0, 0);
#pragma unroll
                for (int q = 0; q < 4; q++) {
                    *(uint4*)(dh + q * 8) = z;
                    *(uint4*)(dl + q * 8) = z;
                }
            }
        }
        // ---- stage B ----
        {
            const __nv_bfloat16* ph = Bhi + (size_t)srow * Ktot + ch * 64 + skq;
            const __nv_bfloat16* pl = Blo + (size_t)srow * Ktot + ch * 64 + skq;
            __nv_bfloat16* dh = sBhi + srow * PA + skq;
            __nv_bfloat16* dl = sBlo + srow * PA + skq;
#pragma unroll
            for (int q = 0; q < 4; q++) {
                *(uint4*)(dh + q * 8) = *(const uint4*)(ph + q * 8);
                *(uint4*)(dl + q * 8) = *(const uint4*)(pl + q * 8);
            }
        }
        __syncthreads();

        // ---- compute: 4 k16 steps ----
#pragma unroll
        for (int ks = 0; ks < 4; ks++) {
            int k0 = ks * 16;
            u32 ahi[2][4], alo[2][4];
#pragma unroll
            for (int mt = 0; mt < 2; mt++) {
                int r = wm * 32 + mt * 16 + g;
                const __nv_bfloat16* base = sAhi + r * PA + k0 + tig * 2;
                ahi[mt][0] = *(const u32*)base;
                ahi[mt][1] = *(const u32*)(base + 8 * PA);
                ahi[mt][2] = *(const u32*)(base + 8);
                ahi[mt][3] = *(const u32*)(base + 8 * PA + 8);
                const __nv_bfloat16* basel = sAlo + r * PA + k0 + tig * 2;
                alo[mt][0] = *(const u32*)basel;
                alo[mt][1] = *(const u32*)(basel + 8 * PA);
                alo[mt][2] = *(const u32*)(basel + 8);
                alo[mt][3] = *(const u32*)(basel + 8 * PA + 8);
            }
#pragma unroll
            for (int nt = 0; nt < 8; nt++) {
                int n = wn * 64 + nt * 8 + g;
                const __nv_bfloat16* bb = sBhi + n * PA + k0 + tig * 2;
                u32 bh0 = *(const u32*)bb;
                u32 bh1 = *(const u32*)(bb + 8);
                const __nv_bfloat16* bl = sBlo + n * PA + k0 + tig * 2;
                u32 bl0 = *(const u32*)bl;
                u32 bl1 = *(const u32*)(bl + 8);
#pragma unroll
                for (int mt = 0; mt < 2; mt++) {
                    mma_bf16(c[mt][nt], ahi[mt], bh0, bh1);
                    mma_bf16(c[mt][nt], alo[mt], bh0, bh1);
                    mma_bf16(c[mt][nt], ahi[mt], bl0, bl1);
                }
            }
        }
    }

    // ---- epilogue ----
    if (h1hi_out) {
#pragma unroll
        for (int mt = 0; mt < 2; mt++) {
            int r0 = nodeBase + wm * 32 + mt * 16 + g;
            int r1 = r0 + 8;
#pragma unroll
            for (int nt = 0; nt < 8; nt++) {
                int col = wn * 64 + nt * 8 + tig * 2;
                if (r0 < N_NODES) {
                    float v0 = fmaxf(c[mt][nt][0] + sBias[col], 0.f);
                    float v1 = fmaxf(c[mt][nt][1] + sBias[col + 1], 0.f);
                    unsigned short h0, l0, h1, l1;
                    split_bf16(v0, h0, l0);
                    split_bf16(v1, h1, l1);
                    size_t o = (size_t)r0 * HID + col;
                    *(u32*)(h1hi_out + o) = (u32)h0 | ((u32)h1 << 16);
                    *(u32*)(h1lo_out + o) = (u32)l0 | ((u32)l1 << 16);
                }
                if (r1 < N_NODES) {
                    float v0 = fmaxf(c[mt][nt][2] + sBias[col], 0.f);
                    float v1 = fmaxf(c[mt][nt][3] + sBias[col + 1], 0.f);
                    unsigned short h0, l0, h1, l1;
                    split_bf16(v0, h0, l0);
                    split_bf16(v1, h1, l1);
                    size_t o = (size_t)r1 * HID + col;
                    *(u32*)(h1hi_out + o) = (u32)h0 | ((u32)h1 << 16);
                    *(u32*)(h1lo_out + o) = (u32)l0 | ((u32)l1 << 16);
                }
            }
        }
    } else {
        float fb0 = __ldg(&fcb[0]), fb1 = __ldg(&fcb[1]);
#pragma unroll
        for (int mt = 0; mt < 2; mt++) {
            float p0a = 0.f, p1a = 0.f, p0b = 0.f, p1b = 0.f;
#pragma unroll
            for (int nt = 0; nt < 8; nt++) {
                int col = wn * 64 + nt * 8 + tig * 2;
                float h0 = fmaxf(c[mt][nt][0] + sBias[col], 0.f);
                float h1 = fmaxf(c[mt][nt][1] + sBias[col + 1], 0.f);
                float h2 = fmaxf(c[mt][nt][2] + sBias[col], 0.f);
                float h3 = fmaxf(c[mt][nt][3] + sBias[col + 1], 0.f);
                p0a += h0 * sFc[col * 2]     + h1 * sFc[(col + 1) * 2];
                p1a += h0 * sFc[col * 2 + 1] + h1 * sFc[(col + 1) * 2 + 1];
                p0b += h2 * sFc[col * 2]     + h3 * sFc[(col + 1) * 2];
                p1b += h2 * sFc[col * 2 + 1] + h3 * sFc[(col + 1) * 2 + 1];
            }
#pragma unroll
            for (int off = 1; off <= 2; off <<= 1) {
                p0a += __shfl_xor_sync(0xFFFFFFFF, p0a, off);
                p1a += __shfl_xor_sync(0xFFFFFFFF, p1a, off);
                p0b += __shfl_xor_sync(0xFFFFFFFF, p0b, off);
                p1b += __shfl_xor_sync(0xFFFFFFFF, p1b, off);
            }
            int r0 = wm * 32 + mt * 16 + g;
            if (tig == 0) {
                float* part = sFc + 256;
                part[(wn * 128 + r0) * 2 + 0] = p0a;
                part[(wn * 128 + r0) * 2 + 1] = p1a;
                part[(wn * 128 + r0 + 8) * 2 + 0] = p0b;
                part[(wn * 128 + r0 + 8) * 2 + 1] = p1b;
            }
        }
        __syncthreads();
        if (t < 256) {
            float* part = sFc + 256;
            int row = t >> 1, chn = t & 1;
            float v = part[row * 2 + chn] + part[(128 + row) * 2 + chn];
            int node = nodeBase + row;
            if (node < N_NODES)
                out[(size_t)node * 2 + chn] = v + ((chn == 0) ? fb0 : fb1);
        }
    }
}

#define SMEM_MMA_TOTAL (4 * 128 * PA * 2 + (128 + 256 + 512) * 4)

// ---------------------------------------------------------------------------
extern "C" void kernel_launch(void* const* d_in, const int* in_sizes, int n_in,
                              void* d_out, int out_size) {
    const float* x   = (const float*)d_in[0];
    const int*   ei  = (const int*)d_in[1];     // int32 (JAX x64 disabled)
    const float* Wn0 = (const float*)d_in[2];
    const float* Ws0 = (const float*)d_in[3];
    const float* b0  = (const float*)d_in[4];
    const float* Wn1 = (const float*)d_in[5];
    const float* Ws1 = (const float*)d_in[6];
    const float* b1  = (const float*)d_in[7];
    const float* fcw = (const float*)d_in[8];
    const float* fcb = (const float*)d_in[9];
    float* out = (float*)d_out;

    void *p_xhi, *p_xlo, *p_m0hi, *p_m0lo, *p_h1hi, *p_h1lo, *p_m1hi, *p_m1lo;
    void *p_B0hi, *p_B0lo, *p_B1hi, *p_B1lo;
    cudaGetSymbolAddress(&p_xhi, g_xhi);
    cudaGetSymbolAddress(&p_xlo, g_xlo);
    cudaGetSymbolAddress(&p_m0hi, g_m0hi);
    cudaGetSymbolAddress(&p_m0lo, g_m0lo);
    cudaGetSymbolAddress(&p_h1hi, g_h1hi);
    cudaGetSymbolAddress(&p_h1lo, g_h1lo);
    cudaGetSymbolAddress(&p_m1hi, g_m1hi);
    cudaGetSymbolAddress(&p_m1lo, g_m1lo);
    cudaGetSymbolAddress(&p_B0hi, g_B0hi);
    cudaGetSymbolAddress(&p_B0lo, g_B0lo);
    cudaGetSymbolAddress(&p_B1hi, g_B1hi);
    cudaGetSymbolAddress(&p_B1lo, g_B1lo);

    // Init (zero deg + weight split) then CSR build
    init_kernel<<<(N_NODES + 255) / 256, 256>>>(Wn0, Ws0, Wn1, Ws1);
    hist_kernel<<<(N_EDGES + 255) / 256, 256>>>(ei);
    scan_phase1_kernel<<<SCAN_BLOCKS, 1024>>>();
    scan_phase2_kernel<<<1, 128>>>();
    scan_phase3_kernel<<<SCAN_BLOCKS, 1024>>>();
    fill_kernel<<<(N_EDGES + 255) / 256, 256>>>(ei);

    cudaFuncSetAttribute(mma_layer_kernel,
                         cudaFuncAttributeMaxDynamicSharedMemorySize, SMEM_MMA_TOTAL);
    int gemmBlocks = (N_NODES + 127) / 128;   // 782

    // Layer 0: h1 = relu([mean0|x] @ [Wn0;Ws0] + b0)   (outputs hi/lo planes)
    gather0_kernel<<<(N_NODES + 7) / 8, 256>>>(x);
    mma_layer_kernel<<<gemmBlocks, 256, SMEM_MMA_TOTAL>>>(
        (const __nv_bfloat16*)p_m0hi, (const __nv_bfloat16*)p_m0lo,
        (const __nv_bfloat16*)p_xhi,  (const __nv_bfloat16*)p_xlo,
        IN_CH, 2,
        (const __nv_bfloat16*)p_B0hi, (const __nv_bfloat16*)p_B0lo, 128,
        b0,
        (__nv_bfloat16*)p_h1hi, (__nv_bfloat16*)p_h1lo,
        nullptr, nullptr, nullptr);

    // Layer 1 + fused FC
    gather1_kernel<<<(N_NODES + 7) / 8, 256>>>();
    mma_layer_kernel<<<gemmBlocks, 256, SMEM_MMA_TOTAL>>>(
        (const __nv_bfloat16*)p_m1hi, (const __nv_bfloat16*)p_m1lo,
        (const __nv_bfloat16*)p_h1hi, (const __nv_bfloat16*)p_h1lo,
        HID, 4,
        (const __nv_bfloat16*)p_B1hi, (const __nv_bfloat16*)p_B1lo, 256,
        b1,
        nullptr, nullptr,
        fcw, fcb, out);
}

// round 13
// speedup vs baseline: 1.1408x; 1.0973x over previous
#include <cuda_runtime.h>
#include <cuda_bf16.h>

#define N_NODES 100000
#define N_EDGES 1600000
#define IN_CH 64
#define HID 128
#define SCAN_BLOCKS 98   // ceil(100000/1024)

typedef unsigned int u32;

// Scratch (static device globals; allocation-free per harness rules)
__device__ int   g_deg[N_NODES];
__device__ int   g_cursor[N_NODES];
__device__ int   g_row_ptr[N_NODES + 1];
__device__ int   g_srcs[N_EDGES];
__device__ int   g_bsum[SCAN_BLOCKS];
__device__ int   g_boff[SCAN_BLOCKS + 1];
// activations as separate bf16 hi/lo planes (split once, copied raw into GEMM)
__device__ __nv_bfloat16 g_xhi[(size_t)N_NODES * IN_CH], g_xlo[(size_t)N_NODES * IN_CH];
__device__ __nv_bfloat16 g_m0hi[(size_t)N_NODES * IN_CH], g_m0lo[(size_t)N_NODES * IN_CH];
__device__ __nv_bfloat16 g_h1hi[(size_t)N_NODES * HID], g_h1lo[(size_t)N_NODES * HID];
__device__ __nv_bfloat16 g_m1hi[(size_t)N_NODES * HID], g_m1lo[(size_t)N_NODES * HID];
// pre-split transposed weights: B[n][k] = W[k][n], bf16 hi/lo, row pitch Ktot
__device__ __nv_bfloat16 g_B0hi[128 * 128], g_B0lo[128 * 128];
__device__ __nv_bfloat16 g_B1hi[128 * 256], g_B1lo[128 * 256];

__device__ __forceinline__ void split_bf16(float v, unsigned short& h, unsigned short& l) {
    __nv_bfloat16 bh = __float2bfloat16(v);
    float r = v - __bfloat162float(bh);
    __nv_bfloat16 bl = __float2bfloat16(r);
    h = __bfloat16_as_ushort(bh);
    l = __bfloat16_as_ushort(bl);
}
__device__ __forceinline__ float bf_lo_f(u32 p) { return __uint_as_float(p << 16); }
__device__ __forceinline__ float bf_hi_f(u32 p) { return __uint_as_float(p & 0xFFFF0000u); }

__device__ __forceinline__ void mma_bf16(float* c, const u32* a, u32 b0, u32 b1) {
    asm volatile(
        "mma.sync.aligned.m16n8k16.row.col.f32.bf16.bf16.f32 "
        "{%0,%1,%2,%3}, {%4,%5,%6,%7}, {%8,%9}, {%0,%1,%2,%3};"
        : "+f"(c[0]), "+f"(c[1]), "+f"(c[2]), "+f"(c[3])
        : "r"(a[0]), "r"(a[1]), "r"(a[2]), "r"(a[3]), "r"(b0), "r"(b1));
}

// ---------------------------------------------------------------------------
// Init: zero degree array + transpose/split both weight matrices
// ---------------------------------------------------------------------------
__global__ void init_kernel(const float* __restrict__ Wn0,
                            const float* __restrict__ Ws0,
                            const float* __restrict__ Wn1,
                            const float* __restrict__ Ws1) {
    int i = blockIdx.x * blockDim.x + threadIdx.x;
    if (i < N_NODES) g_deg[i] = 0;
    if (i < 128 * 256) {
        int n = i >> 8, kk = i & 255;
        float w = (kk < 128) ? Wn1[kk * HID + n] : Ws1[(kk - 128) * HID + n];
        unsigned short h, l;
        split_bf16(w, h, l);
        g_B1hi[i] = __ushort_as_bfloat16(h);
        g_B1lo[i] = __ushort_as_bfloat16(l);
    }
    if (i < 128 * 128) {
        int n = i >> 7, kk = i & 127;
        float w = (kk < 64) ? Wn0[kk * HID + n] : Ws0[(kk - 64) * HID + n];
        unsigned short h, l;
        split_bf16(w, h, l);
        g_B0hi[i] = __ushort_as_bfloat16(h);
        g_B0lo[i] = __ushort_as_bfloat16(l);
    }
}

// ---------------------------------------------------------------------------
// CSR build
// ---------------------------------------------------------------------------
__global__ void hist_kernel(const int* __restrict__ ei) {
    int e = blockIdx.x * blockDim.x + threadIdx.x;
    if (e >= N_EDGES) return;
    atomicAdd(&g_deg[__ldg(&ei[e + N_EDGES])], 1);
}
__global__ __launch_bounds__(1024)
void scan_phase1_kernel() {
    __shared__ int wsum[32];
    int t = threadIdx.x, lane = t & 31, warp = t >> 5;
    int i = blockIdx.x * 1024 + t;
    int v = (i < N_NODES) ? g_deg[i] : 0;
    int inc = v;
#pragma unroll
    for (int off = 1; off < 32; off <<= 1) {
        int n = __shfl_up_sync(0xFFFFFFFF, inc, off);
        if (lane >= off) inc += n;
    }
    if (lane == 31) wsum[warp] = inc;
    __syncthreads();
    if (warp == 0) {
        int w = (lane < 32) ? wsum[lane] : 0;
#pragma unroll
        for (int off = 1; off < 32; off <<= 1) {
            int n = __shfl_up_sync(0xFFFFFFFF, w, off);
            if (lane >= off) w += n;
        }
        wsum[lane] = w;
    }
    __syncthreads();
    int winc = inc + ((warp > 0) ? wsum[warp - 1] : 0);
    if (i < N_NODES) g_cursor[i] = winc;
    if (t == 1023) g_bsum[blockIdx.x] = winc;
}
__global__ void scan_phase2_kernel() {
    __shared__ int sm[SCAN_BLOCKS];
    int t = threadIdx.x;
    if (t < SCAN_BLOCKS) sm[t] = g_bsum[t];
    __syncthreads();
    if (t == 0) {
        int acc = 0;
        for (int i = 0; i < SCAN_BLOCKS; i++) {
            g_boff[i] = acc;
            acc += sm[i];
        }
        g_boff[SCAN_BLOCKS] = acc;
        g_row_ptr[N_NODES] = acc;
    }
}
__global__ __launch_bounds__(1024)
void scan_phase3_kernel() {
    int i = blockIdx.x * 1024 + threadIdx.x;
    if (i >= N_NODES) return;
    int ex = g_boff[blockIdx.x] + g_cursor[i] - g_deg[i];
    g_row_ptr[i] = ex;
    g_cursor[i]  = ex;
}
__global__ void fill_kernel(const int* __restrict__ ei) {
    int e = blockIdx.x * blockDim.x + threadIdx.x;
    if (e >= N_EDGES) return;
    int src = __ldg(&ei[e]);
    int dst = __ldg(&ei[e + N_EDGES]);
    int pos = atomicAdd(&g_cursor[dst], 1);
    g_srcs[pos] = src;
}

// ---------------------------------------------------------------------------
// Gather0: mean of x over in-edges -> m0 hi/lo planes; ALSO splits own x row
// into xhi/xlo (fused prep_x: x row is L2-hot from gathering).
// ---------------------------------------------------------------------------
__global__ void gather0_kernel(const float* __restrict__ x) {
    int node = blockIdx.x * 8 + (threadIdx.x >> 5);
    if (node >= N_NODES) return;
    int lane = threadIdx.x & 31;
    int beg = g_row_ptr[node], end = g_row_ptr[node + 1];
    float2 acc = make_float2(0.f, 0.f);
#pragma unroll 8
    for (int e = beg; e < end; e++) {
        int s = __ldg(&g_srcs[e]);
        float2 v = *(const float2*)(x + (size_t)s * IN_CH + lane * 2);
        acc.x += v.x; acc.y += v.y;
    }
    float inv = 1.0f / fmaxf((float)(end - beg), 1.0f);
    size_t o = (size_t)node * IN_CH + lane * 2;
    {
        unsigned short h0, l0, h1, l1;
        split_bf16(acc.x * inv, h0, l0);
        split_bf16(acc.y * inv, h1, l1);
        *(u32*)(g_m0hi + o) = (u32)h0 | ((u32)h1 << 16);
        *(u32*)(g_m0lo + o) = (u32)l0 | ((u32)l1 << 16);
    }
    {   // fused x split (own row)
        float2 v = *(const float2*)(x + o);
        unsigned short h0, l0, h1, l1;
        split_bf16(v.x, h0, l0);
        split_bf16(v.y, h1, l1);
        *(u32*)(g_xhi + o) = (u32)h0 | ((u32)h1 << 16);
        *(u32*)(g_xlo + o) = (u32)l0 | ((u32)l1 << 16);
    }
}

// Gather1: mean of h1 over in-edges. Reads HI PLANE ONLY (halves L2 traffic;
// bf16 rounding of the mean terms adds ~2e-4 relative error, well under 1e-3).
__global__ void gather1_kernel() {
    int node = blockIdx.x * 8 + (threadIdx.x >> 5);
    if (node >= N_NODES) return;
    int lane = threadIdx.x & 31;
    int beg = g_row_ptr[node], end = g_row_ptr[node + 1];
    float4 acc = make_float4(0.f, 0.f, 0.f, 0.f);
#pragma unroll 8
    for (int e = beg; e < end; e++) {
        int s = __ldg(&g_srcs[e]);
        uint2 vh = *(const uint2*)(g_h1hi + (size_t)s * HID + lane * 4);
        acc.x += bf_lo_f(vh.x);
        acc.y += bf_hi_f(vh.x);
        acc.z += bf_lo_f(vh.y);
        acc.w += bf_hi_f(vh.y);
    }
    float inv = 1.0f / fmaxf((float)(end - beg), 1.0f);
    unsigned short h[4], l[4];
    split_bf16(acc.x * inv, h[0], l[0]);
    split_bf16(acc.y * inv, h[1], l[1]);
    split_bf16(acc.z * inv, h[2], l[2]);
    split_bf16(acc.w * inv, h[3], l[3]);
    size_t o = (size_t)node * HID + lane * 4;
    *(uint2*)(g_m1hi + o) = make_uint2((u32)h[0] | ((u32)h[1] << 16),
                                       (u32)h[2] | ((u32)h[3] << 16));
    *(uint2*)(g_m1lo + o) = make_uint2((u32)l[0] | ((u32)l[1] << 16),
                                       (u32)l[2] | ((u32)l[3] << 16));
}

// ---------------------------------------------------------------------------
// HMMA bf16x3-split GEMM: C[128 nodes][128 out] = [A0|A1] @ B^T (fp32 accum).
// NOTE: no minBlocks clause — (256,2) capped regs at 128 and caused spills (R11).
// ---------------------------------------------------------------------------
#define PA 72   // smem pitch (bf16 elements)

__global__ __launch_bounds__(256)
void mma_layer_kernel(const __nv_bfloat16* __restrict__ A0hi,
                      const __nv_bfloat16* __restrict__ A0lo,
                      const __nv_bfloat16* __restrict__ A1hi,
                      const __nv_bfloat16* __restrict__ A1lo,
                      int rowlen, int nchunk,
                      const __nv_bfloat16* __restrict__ Bhi,
                      const __nv_bfloat16* __restrict__ Blo,
                      int Ktot,
                      const float* __restrict__ bias,
                      __nv_bfloat16* __restrict__ h1hi_out,
                      __nv_bfloat16* __restrict__ h1lo_out,
                      const float* __restrict__ fcw,
                      const float* __restrict__ fcb,
                      float* __restrict__ out) {
    extern __shared__ char smem[];
    __nv_bfloat16* sAhi = (__nv_bfloat16*)smem;
    __nv_bfloat16* sAlo = sAhi + 128 * PA;
    __nv_bfloat16* sBhi = sAlo + 128 * PA;
    __nv_bfloat16* sBlo = sBhi + 128 * PA;
    float* sBias = (float*)(sBlo + 128 * PA);
    float* sFc   = sBias + 128;

    int t = threadIdx.x;
    int wid = t >> 5, lane = t & 31;
    int g = lane >> 2, tig = lane & 3;
    int wm = wid & 3, wn = wid >> 2;
    int nodeBase = blockIdx.x * 128;

    if (t < 128) sBias[t] = bias[t];
    if (out && t < 256) sFc[t] = fcw[t];

    float c[2][8][4];
#pragma unroll
    for (int mt = 0; mt < 2; mt++)
#pragma unroll
        for (int nt = 0; nt < 8; nt++)
#pragma unroll
            for (int q = 0; q < 4; q++) c[mt][nt][q] = 0.f;

    int half = nchunk >> 1;
    int srow = t >> 1;
    int skq  = (t & 1) * 32;

    for (int ch = 0; ch < nchunk; ch++) {
        const __nv_bfloat16* srcHi = (ch < half) ? A0hi : A1hi;
        const __nv_bfloat16* srcLo = (ch < half) ? A0lo : A1lo;
        int kofs = ((ch < half) ? ch : ch - half) * 64;
        __syncthreads();
        // ---- stage A: raw uint4 copies from hi/lo planes ----
        {
            int gn = nodeBase + srow;
            __nv_bfloat16* dh = sAhi + srow * PA + skq;
            __nv_bfloat16* dl = sAlo + srow * PA + skq;
            if (gn < N_NODES) {
                const __nv_bfloat16* ph = srcHi + (size_t)gn * rowlen + kofs + skq;
                const __nv_bfloat16* pl = srcLo + (size_t)gn * rowlen + kofs + skq;
#pragma unroll
                for (int q = 0; q < 4; q++) {
                    *(uint4*)(dh + q * 8) = *(const uint4*)(ph + q * 8);
                    *(uint4*)(dl + q * 8) = *(const uint4*)(pl + q * 8);
                }
            } else {
                uint4 z = make_uint4(0, 0, 0, 0);
#pragma unroll
                for (int q = 0; q < 4; q++) {
                    *(uint4*)(dh + q * 8) = z;
                    *(uint4*)(dl + q * 8) = z;
                }
            }
        }
        // ---- stage B ----
        {
            const __nv_bfloat16* ph = Bhi + (size_t)srow * Ktot + ch * 64 + skq;
            const __nv_bfloat16* pl = Blo + (size_t)srow * Ktot + ch * 64 + skq;
            __nv_bfloat16* dh = sBhi + srow * PA + skq;
            __nv_bfloat16* dl = sBlo + srow * PA + skq;
#pragma unroll
            for (int q = 0; q < 4; q++) {
                *(uint4*)(dh + q * 8) = *(const uint4*)(ph + q * 8);
                *(uint4*)(dl + q * 8) = *(const uint4*)(pl + q * 8);
            }
        }
        __syncthreads();

        // ---- compute: 4 k16 steps ----
#pragma unroll
        for (int ks = 0; ks < 4; ks++) {
            int k0 = ks * 16;
            u32 ahi[2][4], alo[2][4];
#pragma unroll
            for (int mt = 0; mt < 2; mt++) {
                int r = wm * 32 + mt * 16 + g;
                const __nv_bfloat16* base = sAhi + r * PA + k0 + tig * 2;
                ahi[mt][0] = *(const u32*)base;
                ahi[mt][1] = *(const u32*)(base + 8 * PA);
                ahi[mt][2] = *(const u32*)(base + 8);
                ahi[mt][3] = *(const u32*)(base + 8 * PA + 8);
                const __nv_bfloat16* basel = sAlo + r * PA + k0 + tig * 2;
                alo[mt][0] = *(const u32*)basel;
                alo[mt][1] = *(const u32*)(basel + 8 * PA);
                alo[mt][2] = *(const u32*)(basel + 8);
                alo[mt][3] = *(const u32*)(basel + 8 * PA + 8);
            }
#pragma unroll
            for (int nt = 0; nt < 8; nt++) {
                int n = wn * 64 + nt * 8 + g;
                const __nv_bfloat16* bb = sBhi + n * PA + k0 + tig * 2;
                u32 bh0 = *(const u32*)bb;
                u32 bh1 = *(const u32*)(bb + 8);
                const __nv_bfloat16* bl = sBlo + n * PA + k0 + tig * 2;
                u32 bl0 = *(const u32*)bl;
                u32 bl1 = *(const u32*)(bl + 8);
#pragma unroll
                for (int mt = 0; mt < 2; mt++) {
                    mma_bf16(c[mt][nt], ahi[mt], bh0, bh1);
                    mma_bf16(c[mt][nt], alo[mt], bh0, bh1);
                    mma_bf16(c[mt][nt], ahi[mt], bl0, bl1);
                }
            }
        }
    }

    // ---- epilogue ----
    if (h1hi_out) {
#pragma unroll
        for (int mt = 0; mt < 2; mt++) {
            int r0 = nodeBase + wm * 32 + mt * 16 + g;
            int r1 = r0 + 8;
#pragma unroll
            for (int nt = 0; nt < 8; nt++) {
                int col = wn * 64 + nt * 8 + tig * 2;
                if (r0 < N_NODES) {
                    float v0 = fmaxf(c[mt][nt][0] + sBias[col], 0.f);
                    float v1 = fmaxf(c[mt][nt][1] + sBias[col + 1], 0.f);
                    unsigned short h0, l0, h1, l1;
                    split_bf16(v0, h0, l0);
                    split_bf16(v1, h1, l1);
                    size_t o = (size_t)r0 * HID + col;
                    *(u32*)(h1hi_out + o) = (u32)h0 | ((u32)h1 << 16);
                    *(u32*)(h1lo_out + o) = (u32)l0 | ((u32)l1 << 16);
                }
                if (r1 < N_NODES) {
                    float v0 = fmaxf(c[mt][nt][2] + sBias[col], 0.f);
                    float v1 = fmaxf(c[mt][nt][3] + sBias[col + 1], 0.f);
                    unsigned short h0, l0, h1, l1;
                    split_bf16(v0, h0, l0);
                    split_bf16(v1, h1, l1);
                    size_t o = (size_t)r1 * HID + col;
                    *(u32*)(h1hi_out + o) = (u32)h0 | ((u32)h1 << 16);
                    *(u32*)(h1lo_out + o) = (u32)l0 | ((u32)l1 << 16);
                }
            }
        }
    } else {
        float fb0 = __ldg(&fcb[0]), fb1 = __ldg(&fcb[1]);
#pragma unroll
        for (int mt = 0; mt < 2; mt++) {
            float p0a = 0.f, p1a = 0.f, p0b = 0.f, p1b = 0.f;
#pragma unroll
            for (int nt = 0; nt < 8; nt++) {
                int col = wn * 64 + nt * 8 + tig * 2;
                float h0 = fmaxf(c[mt][nt][0] + sBias[col], 0.f);
                float h1 = fmaxf(c[mt][nt][1] + sBias[col + 1], 0.f);
                float h2 = fmaxf(c[mt][nt][2] + sBias[col], 0.f);
                float h3 = fmaxf(c[mt][nt][3] + sBias[col + 1], 0.f);
                p0a += h0 * sFc[col * 2]     + h1 * sFc[(col + 1) * 2];
                p1a += h0 * sFc[col * 2 + 1] + h1 * sFc[(col + 1) * 2 + 1];
                p0b += h2 * sFc[col * 2]     + h3 * sFc[(col + 1) * 2];
                p1b += h2 * sFc[col * 2 + 1] + h3 * sFc[(col + 1) * 2 + 1];
            }
#pragma unroll
            for (int off = 1; off <= 2; off <<= 1) {
                p0a += __shfl_xor_sync(0xFFFFFFFF, p0a, off);
                p1a += __shfl_xor_sync(0xFFFFFFFF, p1a, off);
                p0b += __shfl_xor_sync(0xFFFFFFFF, p0b, off);
                p1b += __shfl_xor_sync(0xFFFFFFFF, p1b, off);
            }
            int r0 = wm * 32 + mt * 16 + g;
            if (tig == 0) {
                float* part = sFc + 256;
                part[(wn * 128 + r0) * 2 + 0] = p0a;
                part[(wn * 128 + r0) * 2 + 1] = p1a;
                part[(wn * 128 + r0 + 8) * 2 + 0] = p0b;
                part[(wn * 128 + r0 + 8) * 2 + 1] = p1b;
            }
        }
        __syncthreads();
        if (t < 256) {
            float* part = sFc + 256;
            int row = t >> 1, chn = t & 1;
            float v = part[row * 2 + chn] + part[(128 + row) * 2 + chn];
            int node = nodeBase + row;
            if (node < N_NODES)
                out[(size_t)node * 2 + chn] = v + ((chn == 0) ? fb0 : fb1);
        }
    }
}

#define SMEM_MMA_TOTAL (4 * 128 * PA * 2 + (128 + 256 + 512) * 4)

// ---------------------------------------------------------------------------
extern "C" void kernel_launch(void* const* d_in, const int* in_sizes, int n_in,
                              void* d_out, int out_size) {
    const float* x   = (const float*)d_in[0];
    const int*   ei  = (const int*)d_in[1];     // int32 (JAX x64 disabled)
    const float* Wn0 = (const float*)d_in[2];
    const float* Ws0 = (const float*)d_in[3];
    const float* b0  = (const float*)d_in[4];
    const float* Wn1 = (const float*)d_in[5];
    const float* Ws1 = (const float*)d_in[6];
    const float* b1  = (const float*)d_in[7];
    const float* fcw = (const float*)d_in[8];
    const float* fcb = (const float*)d_in[9];
    float* out = (float*)d_out;

    void *p_xhi, *p_xlo, *p_m0hi, *p_m0lo, *p_h1hi, *p_h1lo, *p_m1hi, *p_m1lo;
    void *p_B0hi, *p_B0lo, *p_B1hi, *p_B1lo;
    cudaGetSymbolAddress(&p_xhi, g_xhi);
    cudaGetSymbolAddress(&p_xlo, g_xlo);
    cudaGetSymbolAddress(&p_m0hi, g_m0hi);
    cudaGetSymbolAddress(&p_m0lo, g_m0lo);
    cudaGetSymbolAddress(&p_h1hi, g_h1hi);
    cudaGetSymbolAddress(&p_h1lo, g_h1lo);
    cudaGetSymbolAddress(&p_m1hi, g_m1hi);
    cudaGetSymbolAddress(&p_m1lo, g_m1lo);
    cudaGetSymbolAddress(&p_B0hi, g_B0hi);
    cudaGetSymbolAddress(&p_B0lo, g_B0lo);
    cudaGetSymbolAddress(&p_B1hi, g_B1hi);
    cudaGetSymbolAddress(&p_B1lo, g_B1lo);

    // Init (zero deg + weight split) then CSR build
    init_kernel<<<(N_NODES + 255) / 256, 256>>>(Wn0, Ws0, Wn1, Ws1);
    hist_kernel<<<(N_EDGES + 255) / 256, 256>>>(ei);
    scan_phase1_kernel<<<SCAN_BLOCKS, 1024>>>();
    scan_phase2_kernel<<<1, 128>>>();
    scan_phase3_kernel<<<SCAN_BLOCKS, 1024>>>();
    fill_kernel<<<(N_EDGES + 255) / 256, 256>>>(ei);

    cudaFuncSetAttribute(mma_layer_kernel,
                         cudaFuncAttributeMaxDynamicSharedMemorySize, SMEM_MMA_TOTAL);
    int gemmBlocks = (N_NODES + 127) / 128;   // 782

    // Layer 0: h1 = relu([mean0|x] @ [Wn0;Ws0] + b0)   (outputs hi/lo planes)
    gather0_kernel<<<(N_NODES + 7) / 8, 256>>>(x);
    mma_layer_kernel<<<gemmBlocks, 256, SMEM_MMA_TOTAL>>>(
        (const __nv_bfloat16*)p_m0hi, (const __nv_bfloat16*)p_m0lo,
        (const __nv_bfloat16*)p_xhi,  (const __nv_bfloat16*)p_xlo,
        IN_CH, 2,
        (const __nv_bfloat16*)p_B0hi, (const __nv_bfloat16*)p_B0lo, 128,
        b0,
        (__nv_bfloat16*)p_h1hi, (__nv_bfloat16*)p_h1lo,
        nullptr, nullptr, nullptr);

    // Layer 1 + fused FC
    gather1_kernel<<<(N_NODES + 7) / 8, 256>>>();
    mma_layer_kernel<<<gemmBlocks, 256, SMEM_MMA_TOTAL>>>(
        (const __nv_bfloat16*)p_m1hi, (const __nv_bfloat16*)p_m1lo,
        (const __nv_bfloat16*)p_h1hi, (const __nv_bfloat16*)p_h1lo,
        HID, 4,
        (const __nv_bfloat16*)p_B1hi, (const __nv_bfloat16*)p_B1lo, 256,
        b1,
        nullptr, nullptr,
        fcw, fcb, out);
}